// round 10
// baseline (speedup 1.0000x reference)
#include <cuda_runtime.h>
#include <cuda_fp16.h>
#include <cstdint>

#define L_SEQ 4096
#define D_DIM 1024
#define BATCH 4
#define M_TOT 16384

// scratch
__device__ __align__(16) __half g_uprojh[(size_t)M_TOT * D_DIM]; // 32 MB fp16
// g_Uh tiled: [tile_m(128)][kc(32)][row 128][64B] -> 8KB blocks, swizzled
// g_Wh tiled: [tile_n(16)][kc(32)][row 64][64B]   -> 4KB blocks, swizzled
__device__ __align__(16) __half g_Uh[(size_t)M_TOT * D_DIM];  // 32 MB
__device__ __align__(16) __half g_Wh[(size_t)D_DIM * D_DIM];  // 2 MB

__device__ __forceinline__ float silu_f(float x) {
    return x / (1.0f + __expf(-x));
}

__device__ __forceinline__ uint32_t smem_u32(const void* p) {
    uint32_t a;
    asm("{ .reg .u64 t; cvta.to.shared.u64 t, %1; cvt.u32.u64 %0, t; }"
        : "=r"(a) : "l"(p));
    return a;
}

// ---------------------------------------------------------------------------
// Kernel 0: convert U, Wp to fp16 tiled+swizzled.
// ---------------------------------------------------------------------------
#define NCH_U (M_TOT * 128)
#define NCH_W (D_DIM * 128)

__global__ void __launch_bounds__(256)
convert_kernel(const float* __restrict__ U, const float* __restrict__ Wp)
{
    const int stride = gridDim.x * blockDim.x;
    const int tid0 = blockIdx.x * blockDim.x + threadIdx.x;
    for (int j = tid0; j < NCH_U; j += stride) {
        const int c    = j & 3;
        const int r    = (j >> 2) & 127;
        const int kc   = (j >> 9) & 31;
        const int tile = j >> 14;
        const int m    = tile * 128 + r;
        const float4* s = (const float4*)(U + (size_t)m * D_DIM + kc * 32 + c * 8);
        float4 v0 = s[0], v1 = s[1];
        __half2 h0 = __floats2half2_rn(v0.x, v0.y);
        __half2 h1 = __floats2half2_rn(v0.z, v0.w);
        __half2 h2 = __floats2half2_rn(v1.x, v1.y);
        __half2 h3 = __floats2half2_rn(v1.z, v1.w);
        uint4 o;
        o.x = *(const uint32_t*)&h0; o.y = *(const uint32_t*)&h1;
        o.z = *(const uint32_t*)&h2; o.w = *(const uint32_t*)&h3;
        const int csw = c ^ ((r >> 1) & 3);
        const size_t off = ((size_t)(tile * 32 + kc) << 12) + (size_t)r * 32 + csw * 8;
        *(uint4*)(g_Uh + off) = o;
    }
    for (int j = tid0; j < NCH_W; j += stride) {
        const int c    = j & 3;
        const int r    = (j >> 2) & 63;
        const int kc   = (j >> 8) & 31;
        const int tile = j >> 13;
        const int n    = tile * 64 + r;
        const float4* s = (const float4*)(Wp + (size_t)n * D_DIM + kc * 32 + c * 8);
        float4 v0 = s[0], v1 = s[1];
        __half2 h0 = __floats2half2_rn(v0.x, v0.y);
        __half2 h1 = __floats2half2_rn(v0.z, v0.w);
        __half2 h2 = __floats2half2_rn(v1.x, v1.y);
        __half2 h3 = __floats2half2_rn(v1.z, v1.w);
        uint4 o;
        o.x = *(const uint32_t*)&h0; o.y = *(const uint32_t*)&h1;
        o.z = *(const uint32_t*)&h2; o.w = *(const uint32_t*)&h3;
        const int csw = c ^ ((r >> 1) & 3);
        const size_t off = ((size_t)(tile * 32 + kc) << 11) + (size_t)r * 32 + csw * 8;
        *(uint4*)(g_Wh + off) = o;
    }
}

// ---------------------------------------------------------------------------
// Heterogeneous kernel, 4 CTAs/SM (32 warps/SM):
//  bids [0,2048)    = GEMM 128x64 tiles, full/empty mbarrier ring (no BAR)
//  bids [2048,6144) = conv CTAs, CP=16, 48KB smem
// ---------------------------------------------------------------------------
#define GEMM_CTAS 2048
#define CONV_CTAS 4096
#define STAGE_SZ 12288          // A 8KB + B 4KB
#define NSTAGE 3
#define SM_FMB  (NSTAGE * STAGE_SZ)     // 36864: full mbars (3x8)
#define SM_EMB  (SM_FMB + 24)           // empty mbars (3x8)
#define HET_SMEM 49152

#define MBAR_INIT(mbar, cnt) \
    asm volatile("mbarrier.init.shared.b64 [%0], %1;" \
                 :: "r"((uint32_t)(mbar)), "r"((uint32_t)(cnt)) : "memory")
#define MBAR_EXPECT_TX(mbar, bytes) \
    asm volatile("mbarrier.arrive.expect_tx.shared.b64 _, [%0], %1;" \
                 :: "r"((uint32_t)(mbar)), "r"((uint32_t)(bytes)) : "memory")
#define MBAR_ARRIVE(mbar) \
    asm volatile("mbarrier.arrive.shared.b64 _, [%0];" \
                 :: "r"((uint32_t)(mbar)) : "memory")
#define MBAR_WAIT(mbar, ph) do { \
    uint32_t _m = (uint32_t)(mbar); uint32_t _p = (uint32_t)(ph); \
    asm volatile("{\n\t.reg .pred P1;\n\t" \
        "W_%=:\n\t" \
        "mbarrier.try_wait.parity.acquire.cta.shared::cta.b64 P1, [%0], %1, 0x989680;\n\t" \
        "@P1 bra.uni D_%=;\n\t" \
        "bra.uni W_%=;\n\t" \
        "D_%=:\n\t}" :: "r"(_m), "r"(_p) : "memory"); \
} while (0)

__device__ __forceinline__ void bulk_cp(uint32_t dst, const void* src,
                                        uint32_t bytes, uint32_t mbar) {
    asm volatile(
        "cp.async.bulk.shared::cta.global.mbarrier::complete_tx::bytes "
        "[%0], [%1], %2, [%3];"
        :: "r"(dst), "l"(__cvta_generic_to_global(src)), "r"(bytes), "r"(mbar)
        : "memory");
}

__device__ __forceinline__ void ldmatrix4(uint32_t* r, uint32_t addr) {
    asm volatile("ldmatrix.sync.aligned.m8n8.x4.shared.b16 {%0,%1,%2,%3}, [%4];"
                 : "=r"(r[0]), "=r"(r[1]), "=r"(r[2]), "=r"(r[3]) : "r"(addr));
}

__device__ __forceinline__ void mma16816(float* c, const uint32_t* a,
                                         uint32_t b0, uint32_t b1) {
    asm volatile(
        "mma.sync.aligned.m16n8k16.row.col.f32.f16.f16.f32 "
        "{%0,%1,%2,%3}, {%4,%5,%6,%7}, {%8,%9}, {%0,%1,%2,%3};"
        : "+f"(c[0]), "+f"(c[1]), "+f"(c[2]), "+f"(c[3])
        : "r"(a[0]), "r"(a[1]), "r"(a[2]), "r"(a[3]), "r"(b0), "r"(b1));
}

// conv geometry: CP=16 channel pairs (32 channels), 16 workers x 8 outputs
#define CLT 128
#define CP  16
#define CHROWS (CLT + 128)

typedef unsigned long long ull;

__device__ __forceinline__ void ffma2(ull& d, ull a, ull b) {
    asm("fma.rn.f32x2 %0, %1, %2, %0;" : "+l"(d) : "l"(a), "l"(b));
}
__device__ __forceinline__ float2 unpack2(ull v) {
    float2 r;
    asm("mov.b64 {%0,%1}, %2;" : "=f"(r.x), "=f"(r.y) : "l"(v));
    return r;
}

__device__ void gemm_part(char* sm, const float* __restrict__ bp)
{
    const uint32_t sbase = smem_u32(sm);
    const uint32_t fmb   = sbase + SM_FMB;
    const uint32_t emb   = sbase + SM_EMB;
    const int tid  = threadIdx.x;
    const int lane = tid & 31;
    const int warp = tid >> 5;
    const int wm = warp >> 1;     // 0..3  M 32-row slab
    const int wn = warp & 1;      // 0..1  N 32-col slab

    const int t      = blockIdx.x;
    const int tile_m = t >> 4;
    const int tile_n = t & 15;
    const int m0 = tile_m * 128;
    const int n0 = tile_n * 64;

    float c[2][4][4];
    #pragma unroll
    for (int i = 0; i < 2; i++)
        #pragma unroll
        for (int j = 0; j < 4; j++)
            #pragma unroll
            for (int r = 0; r < 4; r++) c[i][j][r] = 0.0f;

    // ldmatrix per-lane offsets (swizzled, 64B rows)
    int offA[2][2], offB[2][2];
    {
        const int c0a = (lane >> 4) & 1;
        const int c0b = (lane >> 3) & 1;
        #pragma unroll
        for (int mt = 0; mt < 2; mt++) {
            int rA = wm * 32 + mt * 16 + (lane & 7) + ((lane >> 3) & 1) * 8;
            int sw = (rA >> 1) & 3;
            #pragma unroll
            for (int kk = 0; kk < 2; kk++)
                offA[mt][kk] = rA * 64 + (((c0a | (kk << 1)) ^ sw) << 4);
        }
        #pragma unroll
        for (int bh = 0; bh < 2; bh++) {
            int rB = wn * 32 + bh * 16 + (lane & 7) + ((lane >> 4) & 1) * 8;
            int sw = (rB >> 1) & 3;
            #pragma unroll
            for (int kk = 0; kk < 2; kk++)
                offB[bh][kk] = 8192 + rB * 64 + (((c0b | (kk << 1)) ^ sw) << 4);
        }
    }

    const char* Abase = (const char*)g_Uh + (size_t)tile_m * 32 * 8192;
    const char* Bbase = (const char*)g_Wh + (size_t)tile_n * 32 * 4096;

    if (tid == 0) {
        #pragma unroll
        for (int i = 0; i < NSTAGE; i++) {
            MBAR_INIT(fmb + i * 8, 1);    // tx-based completion
            MBAR_INIT(emb + i * 8, 8);    // one arrival per warp
        }
        asm volatile("fence.proxy.async.shared::cta;" ::: "memory");
        #pragma unroll
        for (int k0 = 0; k0 < 2; k0++) {
            MBAR_EXPECT_TX(fmb + k0 * 8, STAGE_SZ);
            bulk_cp(sbase + k0 * STAGE_SZ,        Abase + (size_t)k0 * 8192,
                    8192, fmb + k0 * 8);
            bulk_cp(sbase + k0 * STAGE_SZ + 8192, Bbase + (size_t)k0 * 4096,
                    4096, fmb + k0 * 8);
        }
    }
    __syncthreads();   // one-time: mbar init visible before any waits

    for (int kc = 0; kc < 32; kc++) {
        const int s = kc % NSTAGE;

        // producer: load kc+2 into slot (kc+2)%3 once consumers drained kc-1
        if (tid == 0) {
            const int kl = kc + 2;
            if (kl < 32) {
                const int s2 = kl % NSTAGE;
                if (kl >= NSTAGE)
                    MBAR_WAIT(emb + s2 * 8, ((kl - NSTAGE) / NSTAGE) & 1);
                MBAR_EXPECT_TX(fmb + s2 * 8, STAGE_SZ);
                bulk_cp(sbase + s2 * STAGE_SZ,
                        Abase + (size_t)kl * 8192, 8192, fmb + s2 * 8);
                bulk_cp(sbase + s2 * STAGE_SZ + 8192,
                        Bbase + (size_t)kl * 4096, 4096, fmb + s2 * 8);
            }
        }

        MBAR_WAIT(fmb + s * 8, (kc / NSTAGE) & 1);

        const uint32_t stage = sbase + s * STAGE_SZ;
        #pragma unroll
        for (int kk = 0; kk < 2; kk++) {
            uint32_t ar[2][4];
            #pragma unroll
            for (int mt = 0; mt < 2; mt++)
                ldmatrix4(ar[mt], stage + offA[mt][kk]);
            #pragma unroll
            for (int bh = 0; bh < 2; bh++) {
                uint32_t br[4];
                ldmatrix4(br, stage + offB[bh][kk]);
                #pragma unroll
                for (int mt = 0; mt < 2; mt++) {
                    mma16816(c[mt][2 * bh + 0], ar[mt], br[0], br[1]);
                    mma16816(c[mt][2 * bh + 1], ar[mt], br[2], br[3]);
                }
            }
        }
        // warp done with slot s (fragments consumed by mma in program order)
        if (lane == 0) MBAR_ARRIVE(emb + s * 8);
    }

    const int g  = lane >> 2;
    const int tq = lane & 3;
    #pragma unroll
    for (int mt = 0; mt < 2; mt++) {
        const int row = m0 + wm * 32 + mt * 16 + g;
        #pragma unroll
        for (int nt = 0; nt < 4; nt++) {
            const int col = n0 + wn * 32 + nt * 8 + tq * 2;
            float2 bb = *(const float2*)(bp + col);
            __half2 h0 = __floats2half2_rn(silu_f(c[mt][nt][0] + bb.x),
                                           silu_f(c[mt][nt][1] + bb.y));
            __half2 h1 = __floats2half2_rn(silu_f(c[mt][nt][2] + bb.x),
                                           silu_f(c[mt][nt][3] + bb.y));
            *(uint32_t*)(g_uprojh + (size_t)row * D_DIM + col)       = *(uint32_t*)&h0;
            *(uint32_t*)(g_uprojh + (size_t)(row + 8) * D_DIM + col) = *(uint32_t*)&h1;
        }
    }
}

__device__ void conv_part(char* smc,
                          const float* __restrict__ u,
                          const float* __restrict__ w1,
                          const float* __restrict__ b1,
                          const float* __restrict__ w2,
                          const float* __restrict__ b2,
                          float* __restrict__ out)
{
    float2* h_s  = (float2*)smc;                              // [256][16]
    float2* w2_s = (float2*)(smc + CHROWS * CP * 8);          // [128][16]

    const int tid = threadIdx.x;
    const int c   = tid & 15;
    const int yy  = tid >> 4;

    const int idx   = blockIdx.x - GEMM_CTAS;
    const int chunk = idx & 31;
    const int lt    = (idx >> 5) & 31;
    const int bb    = idx >> 10;
    const int tile_start = lt * CLT;
    const int p = chunk * CP + c;

    const float2* uf2  = (const float2*)u + (size_t)bb * L_SEQ * 512;
    const float2* w1f2 = (const float2*)w1;
    const float2* w2f2 = (const float2*)w2;

    #pragma unroll
    for (int i = tid; i < 128 * CP; i += 256) {
        int j = i >> 4, cc = i & 15;
        w2_s[j * CP + cc] = w2f2[(size_t)j * 512 + chunk * CP + cc];
    }

    const float2 w1_0 = w1f2[0 * 512 + p];
    const float2 w1_1 = w1f2[1 * 512 + p];
    const float2 w1_2 = w1f2[2 * 512 + p];
    const float2 b1c  = ((const float2*)b1)[p];

    for (int i = tid; i < CHROWS * CP; i += 256) {
        int hl = i >> 4;
        int l  = tile_start - 127 + hl;
        float2 hv = make_float2(0.0f, 0.0f);
        if (l >= 0 && l < L_SEQ) {
            float2 x2 = uf2[(size_t)l * 512 + p];
            float2 x1 = (l >= 1) ? uf2[(size_t)(l - 1) * 512 + p] : make_float2(0.f, 0.f);
            float2 x0 = (l >= 2) ? uf2[(size_t)(l - 2) * 512 + p] : make_float2(0.f, 0.f);
            float vx = fmaf(x0.x, w1_0.x, fmaf(x1.x, w1_1.x, fmaf(x2.x, w1_2.x, b1c.x)));
            float vy = fmaf(x0.y, w1_0.y, fmaf(x1.y, w1_1.y, fmaf(x2.y, w1_2.y, b1c.y)));
            hv.x = silu_f(vx);
            hv.y = silu_f(vy);
        }
        h_s[hl * CP + c] = hv;
    }
    __syncthreads();

    const int base = yy * 8;
    ull acc[8], win[8];
    #pragma unroll
    for (int r = 0; r < 8; r++) {
        acc[r] = 0ULL;
        win[r] = *(const ull*)&h_s[(base + r) * CP + c];
    }
    #pragma unroll 8
    for (int j = 0; j < 128; j++) {
        ull w = *(const ull*)&w2_s[j * CP + c];
        #pragma unroll
        for (int r = 0; r < 8; r++)
            ffma2(acc[r], win[(j + r) & 7], w);
        win[j & 7] = *(const ull*)&h_s[(base + j + 8) * CP + c];
    }

    const float2 b2c = ((const float2*)b2)[p];
    float2* opf2 = (float2*)out + ((size_t)bb * L_SEQ + tile_start) * 512 + p;

    #pragma unroll
    for (int r = 0; r < 8; r++) {
        float2 a = unpack2(acc[r]);
        int lo   = base + r;
        float2 y;
        y.x = a.x + b2c.x;
        y.y = a.y + b2c.y;
        opf2[(size_t)lo * 512] = y;
    }
}

__global__ void __launch_bounds__(256, 4)
hetero_kernel(const float* __restrict__ u,
              const float* __restrict__ w1,
              const float* __restrict__ b1,
              const float* __restrict__ w2,
              const float* __restrict__ b2,
              const float* __restrict__ bp,
              float* __restrict__ out)
{
    extern __shared__ __align__(128) char sm[];
    if (blockIdx.x < GEMM_CTAS)
        gemm_part(sm, bp);
    else
        conv_part(sm, u, w1, b1, w2, b2, out);
}

// ---------------------------------------------------------------------------
// Final: out *= uproj (fp16 uproj, in place)
// ---------------------------------------------------------------------------
__global__ void __launch_bounds__(256)
mult_kernel(float* __restrict__ out)
{
    const size_t n4 = (size_t)M_TOT * D_DIM / 4;
    const size_t stride = (size_t)gridDim.x * blockDim.x;
    for (size_t i = (size_t)blockIdx.x * blockDim.x + threadIdx.x;
         i < n4; i += stride) {
        float4 o = ((const float4*)out)[i];
        uint2 ph = ((const uint2*)g_uprojh)[i];
        float2 p01 = __half22float2(*(__half2*)&ph.x);
        float2 p23 = __half22float2(*(__half2*)&ph.y);
        o.x *= p01.x; o.y *= p01.y; o.z *= p23.x; o.w *= p23.y;
        ((float4*)out)[i] = o;
    }
}

// ---------------------------------------------------------------------------
extern "C" void kernel_launch(void* const* d_in, const int* in_sizes, int n_in,
                              void* d_out, int out_size)
{
    const float* u  = (const float*)d_in[0];
    const float* w1 = (const float*)d_in[1];
    const float* b1 = (const float*)d_in[2];
    const float* w2 = (const float*)d_in[3];
    const float* b2 = (const float*)d_in[4];
    const float* Wp = (const float*)d_in[5];
    const float* bp = (const float*)d_in[6];
    float* out = (float*)d_out;

    cudaFuncSetAttribute(hetero_kernel,
                         cudaFuncAttributeMaxDynamicSharedMemorySize, HET_SMEM);

    convert_kernel<<<2048, 256>>>(u, Wp);
    hetero_kernel<<<GEMM_CTAS + CONV_CTAS, 256, HET_SMEM>>>(u, w1, b1, w2, b2, bp, out);
    mult_kernel<<<2048, 256>>>(out);
}

// round 11
// speedup vs baseline: 1.0064x; 1.0064x over previous
#include <cuda_runtime.h>
#include <cuda_fp16.h>
#include <cstdint>

#define L_SEQ 4096
#define D_DIM 1024
#define BATCH 4
#define M_TOT 16384

// scratch
__device__ __align__(16) __half g_uprojh[(size_t)M_TOT * D_DIM]; // 32 MB fp16
// g_Uh tiled: [tile_m(128)][kc(32)][row 128][64B] -> 8KB blocks, swizzled
// g_Wh tiled: [tile_n(16)][kc(32)][row 64][64B]   -> 4KB blocks, swizzled
__device__ __align__(16) __half g_Uh[(size_t)M_TOT * D_DIM];  // 32 MB
__device__ __align__(16) __half g_Wh[(size_t)D_DIM * D_DIM];  // 2 MB

__device__ __forceinline__ float silu_f(float x) {
    return x / (1.0f + __expf(-x));
}

__device__ __forceinline__ uint32_t smem_u32(const void* p) {
    uint32_t a;
    asm("{ .reg .u64 t; cvta.to.shared.u64 t, %1; cvt.u32.u64 %0, t; }"
        : "=r"(a) : "l"(p));
    return a;
}

// ---------------------------------------------------------------------------
// Kernel 0: convert U, Wp to fp16 tiled+swizzled.
// ---------------------------------------------------------------------------
#define NCH_U (M_TOT * 128)
#define NCH_W (D_DIM * 128)

__global__ void __launch_bounds__(256)
convert_kernel(const float* __restrict__ U, const float* __restrict__ Wp)
{
    const int stride = gridDim.x * blockDim.x;
    const int tid0 = blockIdx.x * blockDim.x + threadIdx.x;
    for (int j = tid0; j < NCH_U; j += stride) {
        const int c    = j & 3;
        const int r    = (j >> 2) & 127;
        const int kc   = (j >> 9) & 31;
        const int tile = j >> 14;
        const int m    = tile * 128 + r;
        const float4* s = (const float4*)(U + (size_t)m * D_DIM + kc * 32 + c * 8);
        float4 v0 = s[0], v1 = s[1];
        __half2 h0 = __floats2half2_rn(v0.x, v0.y);
        __half2 h1 = __floats2half2_rn(v0.z, v0.w);
        __half2 h2 = __floats2half2_rn(v1.x, v1.y);
        __half2 h3 = __floats2half2_rn(v1.z, v1.w);
        uint4 o;
        o.x = *(const uint32_t*)&h0; o.y = *(const uint32_t*)&h1;
        o.z = *(const uint32_t*)&h2; o.w = *(const uint32_t*)&h3;
        const int csw = c ^ ((r >> 1) & 3);
        const size_t off = ((size_t)(tile * 32 + kc) << 12) + (size_t)r * 32 + csw * 8;
        *(uint4*)(g_Uh + off) = o;
    }
    for (int j = tid0; j < NCH_W; j += stride) {
        const int c    = j & 3;
        const int r    = (j >> 2) & 63;
        const int kc   = (j >> 8) & 31;
        const int tile = j >> 13;
        const int n    = tile * 64 + r;
        const float4* s = (const float4*)(Wp + (size_t)n * D_DIM + kc * 32 + c * 8);
        float4 v0 = s[0], v1 = s[1];
        __half2 h0 = __floats2half2_rn(v0.x, v0.y);
        __half2 h1 = __floats2half2_rn(v0.z, v0.w);
        __half2 h2 = __floats2half2_rn(v1.x, v1.y);
        __half2 h3 = __floats2half2_rn(v1.z, v1.w);
        uint4 o;
        o.x = *(const uint32_t*)&h0; o.y = *(const uint32_t*)&h1;
        o.z = *(const uint32_t*)&h2; o.w = *(const uint32_t*)&h3;
        const int csw = c ^ ((r >> 1) & 3);
        const size_t off = ((size_t)(tile * 32 + kc) << 11) + (size_t)r * 32 + csw * 8;
        *(uint4*)(g_Wh + off) = o;
    }
}

// ---------------------------------------------------------------------------
// Heterogeneous kernel, 4 CTAs/SM (32 warps/SM), INTERLEAVED bids:
//  bid % 3 == 0 -> GEMM tile bid/3   (2048 tiles)
//  else         -> conv index (bid/3)*2 + bid%3 - 1   (4096 CTAs)
// Keeps tensor (GEMM) and fma (conv) pipes co-resident on every SM.
// ---------------------------------------------------------------------------
#define TOTAL_CTAS 6144
#define STAGE_SZ 12288          // A 8KB + B 4KB
#define NSTAGE 3
#define SM_FMB  (NSTAGE * STAGE_SZ)     // 36864: full mbars (3x8)
#define SM_EMB  (SM_FMB + 24)           // empty mbars (3x8)
#define HET_SMEM 49152

#define MBAR_INIT(mbar, cnt) \
    asm volatile("mbarrier.init.shared.b64 [%0], %1;" \
                 :: "r"((uint32_t)(mbar)), "r"((uint32_t)(cnt)) : "memory")
#define MBAR_EXPECT_TX(mbar, bytes) \
    asm volatile("mbarrier.arrive.expect_tx.shared.b64 _, [%0], %1;" \
                 :: "r"((uint32_t)(mbar)), "r"((uint32_t)(bytes)) : "memory")
#define MBAR_ARRIVE(mbar) \
    asm volatile("mbarrier.arrive.shared.b64 _, [%0];" \
                 :: "r"((uint32_t)(mbar)) : "memory")
#define MBAR_WAIT(mbar, ph) do { \
    uint32_t _m = (uint32_t)(mbar); uint32_t _p = (uint32_t)(ph); \
    asm volatile("{\n\t.reg .pred P1;\n\t" \
        "W_%=:\n\t" \
        "mbarrier.try_wait.parity.acquire.cta.shared::cta.b64 P1, [%0], %1, 0x989680;\n\t" \
        "@P1 bra.uni D_%=;\n\t" \
        "bra.uni W_%=;\n\t" \
        "D_%=:\n\t}" :: "r"(_m), "r"(_p) : "memory"); \
} while (0)

__device__ __forceinline__ void bulk_cp(uint32_t dst, const void* src,
                                        uint32_t bytes, uint32_t mbar) {
    asm volatile(
        "cp.async.bulk.shared::cta.global.mbarrier::complete_tx::bytes "
        "[%0], [%1], %2, [%3];"
        :: "r"(dst), "l"(__cvta_generic_to_global(src)), "r"(bytes), "r"(mbar)
        : "memory");
}

__device__ __forceinline__ void ldmatrix4(uint32_t* r, uint32_t addr) {
    asm volatile("ldmatrix.sync.aligned.m8n8.x4.shared.b16 {%0,%1,%2,%3}, [%4];"
                 : "=r"(r[0]), "=r"(r[1]), "=r"(r[2]), "=r"(r[3]) : "r"(addr));
}

__device__ __forceinline__ void mma16816(float* c, const uint32_t* a,
                                         uint32_t b0, uint32_t b1) {
    asm volatile(
        "mma.sync.aligned.m16n8k16.row.col.f32.f16.f16.f32 "
        "{%0,%1,%2,%3}, {%4,%5,%6,%7}, {%8,%9}, {%0,%1,%2,%3};"
        : "+f"(c[0]), "+f"(c[1]), "+f"(c[2]), "+f"(c[3])
        : "r"(a[0]), "r"(a[1]), "r"(a[2]), "r"(a[3]), "r"(b0), "r"(b1));
}

// conv geometry: CP=16 channel pairs (32 channels), 16 workers x 8 outputs
#define CLT 128
#define CP  16
#define CHROWS (CLT + 128)

typedef unsigned long long ull;

__device__ __forceinline__ void ffma2(ull& d, ull a, ull b) {
    asm("fma.rn.f32x2 %0, %1, %2, %0;" : "+l"(d) : "l"(a), "l"(b));
}
__device__ __forceinline__ float2 unpack2(ull v) {
    float2 r;
    asm("mov.b64 {%0,%1}, %2;" : "=f"(r.x), "=f"(r.y) : "l"(v));
    return r;
}

__device__ void gemm_part(char* sm, const float* __restrict__ bp, int t)
{
    const uint32_t sbase = smem_u32(sm);
    const uint32_t fmb   = sbase + SM_FMB;
    const uint32_t emb   = sbase + SM_EMB;
    const int tid  = threadIdx.x;
    const int lane = tid & 31;
    const int warp = tid >> 5;
    const int wm = warp >> 1;     // 0..3  M 32-row slab
    const int wn = warp & 1;      // 0..1  N 32-col slab

    const int tile_m = t >> 4;
    const int tile_n = t & 15;
    const int m0 = tile_m * 128;
    const int n0 = tile_n * 64;

    float c[2][4][4];
    #pragma unroll
    for (int i = 0; i < 2; i++)
        #pragma unroll
        for (int j = 0; j < 4; j++)
            #pragma unroll
            for (int r = 0; r < 4; r++) c[i][j][r] = 0.0f;

    // ldmatrix per-lane offsets (swizzled, 64B rows)
    int offA[2][2], offB[2][2];
    {
        const int c0a = (lane >> 4) & 1;
        const int c0b = (lane >> 3) & 1;
        #pragma unroll
        for (int mt = 0; mt < 2; mt++) {
            int rA = wm * 32 + mt * 16 + (lane & 7) + ((lane >> 3) & 1) * 8;
            int sw = (rA >> 1) & 3;
            #pragma unroll
            for (int kk = 0; kk < 2; kk++)
                offA[mt][kk] = rA * 64 + (((c0a | (kk << 1)) ^ sw) << 4);
        }
        #pragma unroll
        for (int bh = 0; bh < 2; bh++) {
            int rB = wn * 32 + bh * 16 + (lane & 7) + ((lane >> 4) & 1) * 8;
            int sw = (rB >> 1) & 3;
            #pragma unroll
            for (int kk = 0; kk < 2; kk++)
                offB[bh][kk] = 8192 + rB * 64 + (((c0b | (kk << 1)) ^ sw) << 4);
        }
    }

    const char* Abase = (const char*)g_Uh + (size_t)tile_m * 32 * 8192;
    const char* Bbase = (const char*)g_Wh + (size_t)tile_n * 32 * 4096;

    if (tid == 0) {
        #pragma unroll
        for (int i = 0; i < NSTAGE; i++) {
            MBAR_INIT(fmb + i * 8, 1);    // tx-based completion
            MBAR_INIT(emb + i * 8, 8);    // one arrival per warp
        }
        asm volatile("fence.proxy.async.shared::cta;" ::: "memory");
        #pragma unroll
        for (int k0 = 0; k0 < 2; k0++) {
            MBAR_EXPECT_TX(fmb + k0 * 8, STAGE_SZ);
            bulk_cp(sbase + k0 * STAGE_SZ,        Abase + (size_t)k0 * 8192,
                    8192, fmb + k0 * 8);
            bulk_cp(sbase + k0 * STAGE_SZ + 8192, Bbase + (size_t)k0 * 4096,
                    4096, fmb + k0 * 8);
        }
    }
    __syncthreads();   // one-time: mbar init visible before any waits

    for (int kc = 0; kc < 32; kc++) {
        const int s = kc % NSTAGE;

        // producer: load kc+2 into slot (kc+2)%3 once consumers drained kc-1
        if (tid == 0) {
            const int kl = kc + 2;
            if (kl < 32) {
                const int s2 = kl % NSTAGE;
                if (kl >= NSTAGE)
                    MBAR_WAIT(emb + s2 * 8, ((kl - NSTAGE) / NSTAGE) & 1);
                MBAR_EXPECT_TX(fmb + s2 * 8, STAGE_SZ);
                bulk_cp(sbase + s2 * STAGE_SZ,
                        Abase + (size_t)kl * 8192, 8192, fmb + s2 * 8);
                bulk_cp(sbase + s2 * STAGE_SZ + 8192,
                        Bbase + (size_t)kl * 4096, 4096, fmb + s2 * 8);
            }
        }

        MBAR_WAIT(fmb + s * 8, (kc / NSTAGE) & 1);

        const uint32_t stage = sbase + s * STAGE_SZ;
        #pragma unroll
        for (int kk = 0; kk < 2; kk++) {
            uint32_t ar[2][4];
            #pragma unroll
            for (int mt = 0; mt < 2; mt++)
                ldmatrix4(ar[mt], stage + offA[mt][kk]);
            #pragma unroll
            for (int bh = 0; bh < 2; bh++) {
                uint32_t br[4];
                ldmatrix4(br, stage + offB[bh][kk]);
                #pragma unroll
                for (int mt = 0; mt < 2; mt++) {
                    mma16816(c[mt][2 * bh + 0], ar[mt], br[0], br[1]);
                    mma16816(c[mt][2 * bh + 1], ar[mt], br[2], br[3]);
                }
            }
        }
        // warp done with slot s (fragments consumed by mma in program order)
        if (lane == 0) MBAR_ARRIVE(emb + s * 8);
    }

    const int g  = lane >> 2;
    const int tq = lane & 3;
    #pragma unroll
    for (int mt = 0; mt < 2; mt++) {
        const int row = m0 + wm * 32 + mt * 16 + g;
        #pragma unroll
        for (int nt = 0; nt < 4; nt++) {
            const int col = n0 + wn * 32 + nt * 8 + tq * 2;
            float2 bb = *(const float2*)(bp + col);
            __half2 h0 = __floats2half2_rn(silu_f(c[mt][nt][0] + bb.x),
                                           silu_f(c[mt][nt][1] + bb.y));
            __half2 h1 = __floats2half2_rn(silu_f(c[mt][nt][2] + bb.x),
                                           silu_f(c[mt][nt][3] + bb.y));
            *(uint32_t*)(g_uprojh + (size_t)row * D_DIM + col)       = *(uint32_t*)&h0;
            *(uint32_t*)(g_uprojh + (size_t)(row + 8) * D_DIM + col) = *(uint32_t*)&h1;
        }
    }
}

__device__ void conv_part(char* smc, int idx,
                          const float* __restrict__ u,
                          const float* __restrict__ w1,
                          const float* __restrict__ b1,
                          const float* __restrict__ w2,
                          const float* __restrict__ b2,
                          float* __restrict__ out)
{
    float2* h_s  = (float2*)smc;                              // [256][16]
    float2* w2_s = (float2*)(smc + CHROWS * CP * 8);          // [128][16]

    const int tid = threadIdx.x;
    const int c   = tid & 15;
    const int yy  = tid >> 4;

    const int chunk = idx & 31;
    const int lt    = (idx >> 5) & 31;
    const int bb    = idx >> 10;
    const int tile_start = lt * CLT;
    const int p = chunk * CP + c;

    const float2* uf2  = (const float2*)u + (size_t)bb * L_SEQ * 512;
    const float2* w1f2 = (const float2*)w1;
    const float2* w2f2 = (const float2*)w2;

    #pragma unroll
    for (int i = tid; i < 128 * CP; i += 256) {
        int j = i >> 4, cc = i & 15;
        w2_s[j * CP + cc] = w2f2[(size_t)j * 512 + chunk * CP + cc];
    }

    const float2 w1_0 = w1f2[0 * 512 + p];
    const float2 w1_1 = w1f2[1 * 512 + p];
    const float2 w1_2 = w1f2[2 * 512 + p];
    const float2 b1c  = ((const float2*)b1)[p];

    for (int i = tid; i < CHROWS * CP; i += 256) {
        int hl = i >> 4;
        int l  = tile_start - 127 + hl;
        float2 hv = make_float2(0.0f, 0.0f);
        if (l >= 0 && l < L_SEQ) {
            float2 x2 = uf2[(size_t)l * 512 + p];
            float2 x1 = (l >= 1) ? uf2[(size_t)(l - 1) * 512 + p] : make_float2(0.f, 0.f);
            float2 x0 = (l >= 2) ? uf2[(size_t)(l - 2) * 512 + p] : make_float2(0.f, 0.f);
            float vx = fmaf(x0.x, w1_0.x, fmaf(x1.x, w1_1.x, fmaf(x2.x, w1_2.x, b1c.x)));
            float vy = fmaf(x0.y, w1_0.y, fmaf(x1.y, w1_1.y, fmaf(x2.y, w1_2.y, b1c.y)));
            hv.x = silu_f(vx);
            hv.y = silu_f(vy);
        }
        h_s[hl * CP + c] = hv;
    }
    __syncthreads();

    const int base = yy * 8;
    ull acc[8], win[8];
    #pragma unroll
    for (int r = 0; r < 8; r++) {
        acc[r] = 0ULL;
        win[r] = *(const ull*)&h_s[(base + r) * CP + c];
    }
    #pragma unroll 8
    for (int j = 0; j < 128; j++) {
        ull w = *(const ull*)&w2_s[j * CP + c];
        #pragma unroll
        for (int r = 0; r < 8; r++)
            ffma2(acc[r], win[(j + r) & 7], w);
        win[j & 7] = *(const ull*)&h_s[(base + j + 8) * CP + c];
    }

    const float2 b2c = ((const float2*)b2)[p];
    float2* opf2 = (float2*)out + ((size_t)bb * L_SEQ + tile_start) * 512 + p;

    #pragma unroll
    for (int r = 0; r < 8; r++) {
        float2 a = unpack2(acc[r]);
        int lo   = base + r;
        float2 y;
        y.x = a.x + b2c.x;
        y.y = a.y + b2c.y;
        opf2[(size_t)lo * 512] = y;
    }
}

__global__ void __launch_bounds__(256, 4)
hetero_kernel(const float* __restrict__ u,
              const float* __restrict__ w1,
              const float* __restrict__ b1,
              const float* __restrict__ w2,
              const float* __restrict__ b2,
              const float* __restrict__ bp,
              float* __restrict__ out)
{
    extern __shared__ __align__(128) char sm[];
    const int bid = blockIdx.x;
    const int q   = bid / 3;
    const int r   = bid - q * 3;
    if (r == 0)
        gemm_part(sm, bp, q);
    else
        conv_part(sm, q * 2 + (r - 1), u, w1, b1, w2, b2, out);
}

// ---------------------------------------------------------------------------
// Final: out *= uproj (fp16 uproj, in place)
// ---------------------------------------------------------------------------
__global__ void __launch_bounds__(256)
mult_kernel(float* __restrict__ out)
{
    const size_t n4 = (size_t)M_TOT * D_DIM / 4;
    const size_t stride = (size_t)gridDim.x * blockDim.x;
    for (size_t i = (size_t)blockIdx.x * blockDim.x + threadIdx.x;
         i < n4; i += stride) {
        float4 o = ((const float4*)out)[i];
        uint2 ph = ((const uint2*)g_uprojh)[i];
        float2 p01 = __half22float2(*(__half2*)&ph.x);
        float2 p23 = __half22float2(*(__half2*)&ph.y);
        o.x *= p01.x; o.y *= p01.y; o.z *= p23.x; o.w *= p23.y;
        ((float4*)out)[i] = o;
    }
}

// ---------------------------------------------------------------------------
extern "C" void kernel_launch(void* const* d_in, const int* in_sizes, int n_in,
                              void* d_out, int out_size)
{
    const float* u  = (const float*)d_in[0];
    const float* w1 = (const float*)d_in[1];
    const float* b1 = (const float*)d_in[2];
    const float* w2 = (const float*)d_in[3];
    const float* b2 = (const float*)d_in[4];
    const float* Wp = (const float*)d_in[5];
    const float* bp = (const float*)d_in[6];
    float* out = (float*)d_out;

    cudaFuncSetAttribute(hetero_kernel,
                         cudaFuncAttributeMaxDynamicSharedMemorySize, HET_SMEM);

    convert_kernel<<<2048, 256>>>(u, Wp);
    hetero_kernel<<<TOTAL_CTAS, 256, HET_SMEM>>>(u, w1, b1, w2, b2, bp, out);
    mult_kernel<<<2048, 256>>>(out);
}

// round 12
// speedup vs baseline: 1.0524x; 1.0458x over previous
#include <cuda_runtime.h>
#include <cuda_fp16.h>
#include <cstdint>

#define L_SEQ 4096
#define D_DIM 1024
#define BATCH 4
#define M_TOT 16384

// scratch
__device__ __align__(16) __half g_uprojh[(size_t)M_TOT * D_DIM]; // 32 MB fp16
// g_Uh tiled: [tile_m(128)][kc(32)][row 128][64B] -> 8KB blocks, swizzled
// g_Wh tiled: [tile_n(16)][kc(32)][row 64][64B]   -> 4KB blocks, swizzled
__device__ __align__(16) __half g_Uh[(size_t)M_TOT * D_DIM];  // 32 MB
__device__ __align__(16) __half g_Wh[(size_t)D_DIM * D_DIM];  // 2 MB
// per-GEMM-tile done flags (tile index = tile_m*16 + tile_n)
__device__ int g_flag[2048];

__device__ __forceinline__ float silu_f(float x) {
    return x / (1.0f + __expf(-x));
}

__device__ __forceinline__ uint32_t smem_u32(const void* p) {
    uint32_t a;
    asm("{ .reg .u64 t; cvta.to.shared.u64 t, %1; cvt.u32.u64 %0, t; }"
        : "=r"(a) : "l"(p));
    return a;
}

// ---------------------------------------------------------------------------
// Kernel 0: convert U, Wp to fp16 tiled+swizzled; zero flags.
// ---------------------------------------------------------------------------
#define NCH_U (M_TOT * 128)
#define NCH_W (D_DIM * 128)

__global__ void __launch_bounds__(256)
convert_kernel(const float* __restrict__ U, const float* __restrict__ Wp)
{
    if (blockIdx.x == 0) {
        for (int i = threadIdx.x; i < 2048; i += 256) g_flag[i] = 0;
    }
    const int stride = gridDim.x * blockDim.x;
    const int tid0 = blockIdx.x * blockDim.x + threadIdx.x;
    for (int j = tid0; j < NCH_U; j += stride) {
        const int c    = j & 3;
        const int r    = (j >> 2) & 127;
        const int kc   = (j >> 9) & 31;
        const int tile = j >> 14;
        const int m    = tile * 128 + r;
        const float4* s = (const float4*)(U + (size_t)m * D_DIM + kc * 32 + c * 8);
        float4 v0 = s[0], v1 = s[1];
        __half2 h0 = __floats2half2_rn(v0.x, v0.y);
        __half2 h1 = __floats2half2_rn(v0.z, v0.w);
        __half2 h2 = __floats2half2_rn(v1.x, v1.y);
        __half2 h3 = __floats2half2_rn(v1.z, v1.w);
        uint4 o;
        o.x = *(const uint32_t*)&h0; o.y = *(const uint32_t*)&h1;
        o.z = *(const uint32_t*)&h2; o.w = *(const uint32_t*)&h3;
        const int csw = c ^ ((r >> 1) & 3);
        const size_t off = ((size_t)(tile * 32 + kc) << 12) + (size_t)r * 32 + csw * 8;
        *(uint4*)(g_Uh + off) = o;
    }
    for (int j = tid0; j < NCH_W; j += stride) {
        const int c    = j & 3;
        const int r    = (j >> 2) & 63;
        const int kc   = (j >> 8) & 31;
        const int tile = j >> 13;
        const int n    = tile * 64 + r;
        const float4* s = (const float4*)(Wp + (size_t)n * D_DIM + kc * 32 + c * 8);
        float4 v0 = s[0], v1 = s[1];
        __half2 h0 = __floats2half2_rn(v0.x, v0.y);
        __half2 h1 = __floats2half2_rn(v0.z, v0.w);
        __half2 h2 = __floats2half2_rn(v1.x, v1.y);
        __half2 h3 = __floats2half2_rn(v1.z, v1.w);
        uint4 o;
        o.x = *(const uint32_t*)&h0; o.y = *(const uint32_t*)&h1;
        o.z = *(const uint32_t*)&h2; o.w = *(const uint32_t*)&h3;
        const int csw = c ^ ((r >> 1) & 3);
        const size_t off = ((size_t)(tile * 32 + kc) << 11) + (size_t)r * 32 + csw * 8;
        *(uint4*)(g_Wh + off) = o;
    }
}

// ---------------------------------------------------------------------------
// Heterogeneous kernel, 4 CTAs/SM (32 warps/SM). Bid layout gives conv CTAs
// ~2.6 waves of slack behind their producing GEMM tile:
//   bids [0,512)        : GEMM tiles 0..511 (prefix)
//   bids [512,5120)     : r==0 -> GEMM tile 512+q ; else conv idx q*2+(r-1)
//   bids [5120,6144)    : conv idx 3072..4095 (tail)
// Conv epilogue waits on per-tile flag, multiplies uproj inline (no mult pass)
// ---------------------------------------------------------------------------
#define TOTAL_CTAS 6144
#define STAGE_SZ 12288          // A 8KB + B 4KB
#define NSTAGE 3
#define SM_FMB  (NSTAGE * STAGE_SZ)     // 36864: full mbars (3x8)
#define SM_EMB  (SM_FMB + 24)           // empty mbars (3x8)
#define HET_SMEM 49152

#define MBAR_INIT(mbar, cnt) \
    asm volatile("mbarrier.init.shared.b64 [%0], %1;" \
                 :: "r"((uint32_t)(mbar)), "r"((uint32_t)(cnt)) : "memory")
#define MBAR_EXPECT_TX(mbar, bytes) \
    asm volatile("mbarrier.arrive.expect_tx.shared.b64 _, [%0], %1;" \
                 :: "r"((uint32_t)(mbar)), "r"((uint32_t)(bytes)) : "memory")
#define MBAR_ARRIVE(mbar) \
    asm volatile("mbarrier.arrive.shared.b64 _, [%0];" \
                 :: "r"((uint32_t)(mbar)) : "memory")
#define MBAR_WAIT(mbar, ph) do { \
    uint32_t _m = (uint32_t)(mbar); uint32_t _p = (uint32_t)(ph); \
    asm volatile("{\n\t.reg .pred P1;\n\t" \
        "W_%=:\n\t" \
        "mbarrier.try_wait.parity.acquire.cta.shared::cta.b64 P1, [%0], %1, 0x989680;\n\t" \
        "@P1 bra.uni D_%=;\n\t" \
        "bra.uni W_%=;\n\t" \
        "D_%=:\n\t}" :: "r"(_m), "r"(_p) : "memory"); \
} while (0)

__device__ __forceinline__ void bulk_cp(uint32_t dst, const void* src,
                                        uint32_t bytes, uint32_t mbar) {
    asm volatile(
        "cp.async.bulk.shared::cta.global.mbarrier::complete_tx::bytes "
        "[%0], [%1], %2, [%3];"
        :: "r"(dst), "l"(__cvta_generic_to_global(src)), "r"(bytes), "r"(mbar)
        : "memory");
}

__device__ __forceinline__ void ldmatrix4(uint32_t* r, uint32_t addr) {
    asm volatile("ldmatrix.sync.aligned.m8n8.x4.shared.b16 {%0,%1,%2,%3}, [%4];"
                 : "=r"(r[0]), "=r"(r[1]), "=r"(r[2]), "=r"(r[3]) : "r"(addr));
}

__device__ __forceinline__ void mma16816(float* c, const uint32_t* a,
                                         uint32_t b0, uint32_t b1) {
    asm volatile(
        "mma.sync.aligned.m16n8k16.row.col.f32.f16.f16.f32 "
        "{%0,%1,%2,%3}, {%4,%5,%6,%7}, {%8,%9}, {%0,%1,%2,%3};"
        : "+f"(c[0]), "+f"(c[1]), "+f"(c[2]), "+f"(c[3])
        : "r"(a[0]), "r"(a[1]), "r"(a[2]), "r"(a[3]), "r"(b0), "r"(b1));
}

// conv geometry: CP=16 channel pairs (32 channels), 16 workers x 8 outputs
#define CLT 128
#define CP  16
#define CHROWS (CLT + 128)

typedef unsigned long long ull;

__device__ __forceinline__ void ffma2(ull& d, ull a, ull b) {
    asm("fma.rn.f32x2 %0, %1, %2, %0;" : "+l"(d) : "l"(a), "l"(b));
}
__device__ __forceinline__ float2 unpack2(ull v) {
    float2 r;
    asm("mov.b64 {%0,%1}, %2;" : "=f"(r.x), "=f"(r.y) : "l"(v));
    return r;
}

__device__ void gemm_part(char* sm, const float* __restrict__ bp, int t)
{
    const uint32_t sbase = smem_u32(sm);
    const uint32_t fmb   = sbase + SM_FMB;
    const uint32_t emb   = sbase + SM_EMB;
    const int tid  = threadIdx.x;
    const int lane = tid & 31;
    const int warp = tid >> 5;
    const int wm = warp >> 1;     // 0..3  M 32-row slab
    const int wn = warp & 1;      // 0..1  N 32-col slab

    const int tile_m = t >> 4;
    const int tile_n = t & 15;
    const int m0 = tile_m * 128;
    const int n0 = tile_n * 64;

    float c[2][4][4];
    #pragma unroll
    for (int i = 0; i < 2; i++)
        #pragma unroll
        for (int j = 0; j < 4; j++)
            #pragma unroll
            for (int r = 0; r < 4; r++) c[i][j][r] = 0.0f;

    // ldmatrix per-lane offsets (swizzled, 64B rows)
    int offA[2][2], offB[2][2];
    {
        const int c0a = (lane >> 4) & 1;
        const int c0b = (lane >> 3) & 1;
        #pragma unroll
        for (int mt = 0; mt < 2; mt++) {
            int rA = wm * 32 + mt * 16 + (lane & 7) + ((lane >> 3) & 1) * 8;
            int sw = (rA >> 1) & 3;
            #pragma unroll
            for (int kk = 0; kk < 2; kk++)
                offA[mt][kk] = rA * 64 + (((c0a | (kk << 1)) ^ sw) << 4);
        }
        #pragma unroll
        for (int bh = 0; bh < 2; bh++) {
            int rB = wn * 32 + bh * 16 + (lane & 7) + ((lane >> 4) & 1) * 8;
            int sw = (rB >> 1) & 3;
            #pragma unroll
            for (int kk = 0; kk < 2; kk++)
                offB[bh][kk] = 8192 + rB * 64 + (((c0b | (kk << 1)) ^ sw) << 4);
        }
    }

    const char* Abase = (const char*)g_Uh + (size_t)tile_m * 32 * 8192;
    const char* Bbase = (const char*)g_Wh + (size_t)tile_n * 32 * 4096;

    if (tid == 0) {
        #pragma unroll
        for (int i = 0; i < NSTAGE; i++) {
            MBAR_INIT(fmb + i * 8, 1);    // tx-based completion
            MBAR_INIT(emb + i * 8, 8);    // one arrival per warp
        }
        asm volatile("fence.proxy.async.shared::cta;" ::: "memory");
        #pragma unroll
        for (int k0 = 0; k0 < 2; k0++) {
            MBAR_EXPECT_TX(fmb + k0 * 8, STAGE_SZ);
            bulk_cp(sbase + k0 * STAGE_SZ,        Abase + (size_t)k0 * 8192,
                    8192, fmb + k0 * 8);
            bulk_cp(sbase + k0 * STAGE_SZ + 8192, Bbase + (size_t)k0 * 4096,
                    4096, fmb + k0 * 8);
        }
    }
    __syncthreads();   // one-time: mbar init visible before any waits

    for (int kc = 0; kc < 32; kc++) {
        const int s = kc % NSTAGE;

        // producer: load kc+2 into slot (kc+2)%3 once consumers drained kc-1
        if (tid == 0) {
            const int kl = kc + 2;
            if (kl < 32) {
                const int s2 = kl % NSTAGE;
                if (kl >= NSTAGE)
                    MBAR_WAIT(emb + s2 * 8, ((kl - NSTAGE) / NSTAGE) & 1);
                MBAR_EXPECT_TX(fmb + s2 * 8, STAGE_SZ);
                bulk_cp(sbase + s2 * STAGE_SZ,
                        Abase + (size_t)kl * 8192, 8192, fmb + s2 * 8);
                bulk_cp(sbase + s2 * STAGE_SZ + 8192,
                        Bbase + (size_t)kl * 4096, 4096, fmb + s2 * 8);
            }
        }

        MBAR_WAIT(fmb + s * 8, (kc / NSTAGE) & 1);

        const uint32_t stage = sbase + s * STAGE_SZ;
        #pragma unroll
        for (int kk = 0; kk < 2; kk++) {
            uint32_t ar[2][4];
            #pragma unroll
            for (int mt = 0; mt < 2; mt++)
                ldmatrix4(ar[mt], stage + offA[mt][kk]);
            #pragma unroll
            for (int bh = 0; bh < 2; bh++) {
                uint32_t br[4];
                ldmatrix4(br, stage + offB[bh][kk]);
                #pragma unroll
                for (int mt = 0; mt < 2; mt++) {
                    mma16816(c[mt][2 * bh + 0], ar[mt], br[0], br[1]);
                    mma16816(c[mt][2 * bh + 1], ar[mt], br[2], br[3]);
                }
            }
        }
        // warp done with slot s (fragments consumed by mma in program order)
        if (lane == 0) MBAR_ARRIVE(emb + s * 8);
    }

    const int g  = lane >> 2;
    const int tq = lane & 3;
    #pragma unroll
    for (int mt = 0; mt < 2; mt++) {
        const int row = m0 + wm * 32 + mt * 16 + g;
        #pragma unroll
        for (int nt = 0; nt < 4; nt++) {
            const int col = n0 + wn * 32 + nt * 8 + tq * 2;
            float2 bb = *(const float2*)(bp + col);
            __half2 h0 = __floats2half2_rn(silu_f(c[mt][nt][0] + bb.x),
                                           silu_f(c[mt][nt][1] + bb.y));
            __half2 h1 = __floats2half2_rn(silu_f(c[mt][nt][2] + bb.x),
                                           silu_f(c[mt][nt][3] + bb.y));
            *(uint32_t*)(g_uprojh + (size_t)row * D_DIM + col)       = *(uint32_t*)&h0;
            *(uint32_t*)(g_uprojh + (size_t)(row + 8) * D_DIM + col) = *(uint32_t*)&h1;
        }
    }

    // release: make uproj stores visible, then flag tile done
    __syncthreads();
    if (tid == 0) {
        int* f = &g_flag[t];
        asm volatile("st.release.gpu.global.b32 [%0], %1;"
                     :: "l"(f), "r"(1) : "memory");
    }
}

__device__ void conv_part(char* smc, int idx,
                          const float* __restrict__ u,
                          const float* __restrict__ w1,
                          const float* __restrict__ b1,
                          const float* __restrict__ w2,
                          const float* __restrict__ b2,
                          float* __restrict__ out)
{
    float2* h_s  = (float2*)smc;                              // [256][16]
    float2* w2_s = (float2*)(smc + CHROWS * CP * 8);          // [128][16]

    const int tid = threadIdx.x;
    const int c   = tid & 15;
    const int yy  = tid >> 4;

    const int chunk = idx & 31;
    const int lt    = (idx >> 5) & 31;
    const int bb    = idx >> 10;
    const int tile_start = lt * CLT;
    const int p = chunk * CP + c;

    const float2* uf2  = (const float2*)u + (size_t)bb * L_SEQ * 512;
    const float2* w1f2 = (const float2*)w1;
    const float2* w2f2 = (const float2*)w2;

    #pragma unroll
    for (int i = tid; i < 128 * CP; i += 256) {
        int j = i >> 4, cc = i & 15;
        w2_s[j * CP + cc] = w2f2[(size_t)j * 512 + chunk * CP + cc];
    }

    const float2 w1_0 = w1f2[0 * 512 + p];
    const float2 w1_1 = w1f2[1 * 512 + p];
    const float2 w1_2 = w1f2[2 * 512 + p];
    const float2 b1c  = ((const float2*)b1)[p];

    for (int i = tid; i < CHROWS * CP; i += 256) {
        int hl = i >> 4;
        int l  = tile_start - 127 + hl;
        float2 hv = make_float2(0.0f, 0.0f);
        if (l >= 0 && l < L_SEQ) {
            float2 x2 = uf2[(size_t)l * 512 + p];
            float2 x1 = (l >= 1) ? uf2[(size_t)(l - 1) * 512 + p] : make_float2(0.f, 0.f);
            float2 x0 = (l >= 2) ? uf2[(size_t)(l - 2) * 512 + p] : make_float2(0.f, 0.f);
            float vx = fmaf(x0.x, w1_0.x, fmaf(x1.x, w1_1.x, fmaf(x2.x, w1_2.x, b1c.x)));
            float vy = fmaf(x0.y, w1_0.y, fmaf(x1.y, w1_1.y, fmaf(x2.y, w1_2.y, b1c.y)));
            hv.x = silu_f(vx);
            hv.y = silu_f(vy);
        }
        h_s[hl * CP + c] = hv;
    }
    __syncthreads();

    const int base = yy * 8;
    ull acc[8], win[8];
    #pragma unroll
    for (int r = 0; r < 8; r++) {
        acc[r] = 0ULL;
        win[r] = *(const ull*)&h_s[(base + r) * CP + c];
    }
    #pragma unroll 8
    for (int j = 0; j < 128; j++) {
        ull w = *(const ull*)&w2_s[j * CP + c];
        #pragma unroll
        for (int r = 0; r < 8; r++)
            ffma2(acc[r], win[(j + r) & 7], w);
        win[j & 7] = *(const ull*)&h_s[(base + j + 8) * CP + c];
    }

    // wait for producing GEMM tile (scheduled ~2.6 waves earlier; w.h.p. done)
    const int t_needed = (bb * 32 + lt) * 16 + (chunk >> 1);
    if (tid == 0) {
        const int* f = &g_flag[t_needed];
        int v;
        do {
            asm volatile("ld.acquire.gpu.global.b32 %0, [%1];"
                         : "=r"(v) : "l"(f) : "memory");
            if (!v) __nanosleep(64);
        } while (!v);
    }
    __syncthreads();

    const float2 b2c = ((const float2*)b2)[p];
    const uint32_t* upf = (const uint32_t*)g_uprojh
                          + ((size_t)bb * L_SEQ + tile_start) * 512 + p;
    float2* opf2 = (float2*)out + ((size_t)bb * L_SEQ + tile_start) * 512 + p;

    #pragma unroll
    for (int r = 0; r < 8; r++) {
        float2 a = unpack2(acc[r]);
        int lo   = base + r;
        uint32_t ph = upf[(size_t)lo * 512];
        float2 pr = __half22float2(*(__half2*)&ph);
        float2 y;
        y.x = (a.x + b2c.x) * pr.x;
        y.y = (a.y + b2c.y) * pr.y;
        opf2[(size_t)lo * 512] = y;
    }
}

__global__ void __launch_bounds__(256, 4)
hetero_kernel(const float* __restrict__ u,
              const float* __restrict__ w1,
              const float* __restrict__ b1,
              const float* __restrict__ w2,
              const float* __restrict__ b2,
              const float* __restrict__ bp,
              float* __restrict__ out)
{
    extern __shared__ __align__(128) char sm[];
    const int bid = blockIdx.x;
    if (bid < 512) {
        gemm_part(sm, bp, bid);
    } else if (bid < 5120) {
        const int q = (bid - 512) / 3;
        const int r = (bid - 512) - q * 3;
        if (r == 0)
            gemm_part(sm, bp, 512 + q);
        else
            conv_part(sm, q * 2 + (r - 1), u, w1, b1, w2, b2, out);
    } else {
        conv_part(sm, 3072 + (bid - 5120), u, w1, b1, w2, b2, out);
    }
}

// ---------------------------------------------------------------------------
extern "C" void kernel_launch(void* const* d_in, const int* in_sizes, int n_in,
                              void* d_out, int out_size)
{
    const float* u  = (const float*)d_in[0];
    const float* w1 = (const float*)d_in[1];
    const float* b1 = (const float*)d_in[2];
    const float* w2 = (const float*)d_in[3];
    const float* b2 = (const float*)d_in[4];
    const float* Wp = (const float*)d_in[5];
    const float* bp = (const float*)d_in[6];
    float* out = (float*)d_out;

    cudaFuncSetAttribute(hetero_kernel,
                         cudaFuncAttributeMaxDynamicSharedMemorySize, HET_SMEM);

    convert_kernel<<<2048, 256>>>(u, Wp);
    hetero_kernel<<<TOTAL_CTAS, 256, HET_SMEM>>>(u, w1, b1, w2, b2, bp, out);
}

// round 13
// speedup vs baseline: 1.0856x; 1.0315x over previous
#include <cuda_runtime.h>
#include <cuda_fp16.h>
#include <cstdint>

#define L_SEQ 4096
#define D_DIM 1024
#define BATCH 4
#define M_TOT 16384

// scratch
__device__ __align__(16) __half g_uprojh[(size_t)M_TOT * D_DIM]; // 32 MB fp16
// g_Uh tiled: [tile_m(128)][kc(32)][row 128][64B] -> 8KB blocks, swizzled
// g_Wh tiled: [tile_n(16)][kc(32)][row 64][64B]   -> 4KB blocks, swizzled
__device__ __align__(16) __half g_Uh[(size_t)M_TOT * D_DIM];  // 32 MB
__device__ __align__(16) __half g_Wh[(size_t)D_DIM * D_DIM];  // 2 MB
// per-GEMM-tile done flags (tile index = tile_m*16 + tile_n)
__device__ int g_flag[2048];

__device__ __forceinline__ float silu_f(float x) {
    return x / (1.0f + __expf(-x));
}

__device__ __forceinline__ uint32_t smem_u32(const void* p) {
    uint32_t a;
    asm("{ .reg .u64 t; cvta.to.shared.u64 t, %1; cvt.u32.u64 %0, t; }"
        : "=r"(a) : "l"(p));
    return a;
}

// ---------------------------------------------------------------------------
// Kernel 0: convert U, Wp to fp16 tiled+swizzled; zero flags.
// ---------------------------------------------------------------------------
#define NCH_U (M_TOT * 128)
#define NCH_W (D_DIM * 128)

__global__ void __launch_bounds__(256)
convert_kernel(const float* __restrict__ U, const float* __restrict__ Wp)
{
    if (blockIdx.x == 0) {
        for (int i = threadIdx.x; i < 2048; i += 256) g_flag[i] = 0;
    }
    const int stride = gridDim.x * blockDim.x;
    const int tid0 = blockIdx.x * blockDim.x + threadIdx.x;
    for (int j = tid0; j < NCH_U; j += stride) {
        const int c    = j & 3;
        const int r    = (j >> 2) & 127;
        const int kc   = (j >> 9) & 31;
        const int tile = j >> 14;
        const int m    = tile * 128 + r;
        const float4* s = (const float4*)(U + (size_t)m * D_DIM + kc * 32 + c * 8);
        float4 v0 = s[0], v1 = s[1];
        __half2 h0 = __floats2half2_rn(v0.x, v0.y);
        __half2 h1 = __floats2half2_rn(v0.z, v0.w);
        __half2 h2 = __floats2half2_rn(v1.x, v1.y);
        __half2 h3 = __floats2half2_rn(v1.z, v1.w);
        uint4 o;
        o.x = *(const uint32_t*)&h0; o.y = *(const uint32_t*)&h1;
        o.z = *(const uint32_t*)&h2; o.w = *(const uint32_t*)&h3;
        const int csw = c ^ ((r >> 1) & 3);
        const size_t off = ((size_t)(tile * 32 + kc) << 12) + (size_t)r * 32 + csw * 8;
        *(uint4*)(g_Uh + off) = o;
    }
    for (int j = tid0; j < NCH_W; j += stride) {
        const int c    = j & 3;
        const int r    = (j >> 2) & 63;
        const int kc   = (j >> 8) & 31;
        const int tile = j >> 13;
        const int n    = tile * 64 + r;
        const float4* s = (const float4*)(Wp + (size_t)n * D_DIM + kc * 32 + c * 8);
        float4 v0 = s[0], v1 = s[1];
        __half2 h0 = __floats2half2_rn(v0.x, v0.y);
        __half2 h1 = __floats2half2_rn(v0.z, v0.w);
        __half2 h2 = __floats2half2_rn(v1.x, v1.y);
        __half2 h3 = __floats2half2_rn(v1.z, v1.w);
        uint4 o;
        o.x = *(const uint32_t*)&h0; o.y = *(const uint32_t*)&h1;
        o.z = *(const uint32_t*)&h2; o.w = *(const uint32_t*)&h3;
        const int csw = c ^ ((r >> 1) & 3);
        const size_t off = ((size_t)(tile * 32 + kc) << 11) + (size_t)r * 32 + csw * 8;
        *(uint4*)(g_Wh + off) = o;
    }
}

// ---------------------------------------------------------------------------
// Heterogeneous kernel, 4 CTAs/SM (32 warps/SM). Bid layout gives conv CTAs
// ~2.6 waves of slack behind their producing GEMM tile:
//   bids [0,512)        : GEMM tiles 0..511 (prefix)
//   bids [512,5120)     : r==0 -> GEMM tile 512+q ; else conv idx q*2+(r-1)
//   bids [5120,6144)    : conv idx 3072..4095 (tail)
// GEMM: BK=64 (2 kc per stage), 2-stage double buffer -> 16 syncs per tile.
// ---------------------------------------------------------------------------
#define TOTAL_CTAS 6144
#define STAGE_SZ 24576          // A 16KB + B 8KB (2 kc)
#define NITER 16
#define SM_FMB  (2 * STAGE_SZ)          // 49152: full mbars (2x8)
#define SM_EMB  (SM_FMB + 16)           // empty mbars (2x8)
#define HET_SMEM 49664

#define MBAR_INIT(mbar, cnt) \
    asm volatile("mbarrier.init.shared.b64 [%0], %1;" \
                 :: "r"((uint32_t)(mbar)), "r"((uint32_t)(cnt)) : "memory")
#define MBAR_EXPECT_TX(mbar, bytes) \
    asm volatile("mbarrier.arrive.expect_tx.shared.b64 _, [%0], %1;" \
                 :: "r"((uint32_t)(mbar)), "r"((uint32_t)(bytes)) : "memory")
#define MBAR_ARRIVE(mbar) \
    asm volatile("mbarrier.arrive.shared.b64 _, [%0];" \
                 :: "r"((uint32_t)(mbar)) : "memory")
#define MBAR_WAIT(mbar, ph) do { \
    uint32_t _m = (uint32_t)(mbar); uint32_t _p = (uint32_t)(ph); \
    asm volatile("{\n\t.reg .pred P1;\n\t" \
        "W_%=:\n\t" \
        "mbarrier.try_wait.parity.acquire.cta.shared::cta.b64 P1, [%0], %1, 0x989680;\n\t" \
        "@P1 bra.uni D_%=;\n\t" \
        "bra.uni W_%=;\n\t" \
        "D_%=:\n\t}" :: "r"(_m), "r"(_p) : "memory"); \
} while (0)

__device__ __forceinline__ void bulk_cp(uint32_t dst, const void* src,
                                        uint32_t bytes, uint32_t mbar) {
    asm volatile(
        "cp.async.bulk.shared::cta.global.mbarrier::complete_tx::bytes "
        "[%0], [%1], %2, [%3];"
        :: "r"(dst), "l"(__cvta_generic_to_global(src)), "r"(bytes), "r"(mbar)
        : "memory");
}

__device__ __forceinline__ void ldmatrix4(uint32_t* r, uint32_t addr) {
    asm volatile("ldmatrix.sync.aligned.m8n8.x4.shared.b16 {%0,%1,%2,%3}, [%4];"
                 : "=r"(r[0]), "=r"(r[1]), "=r"(r[2]), "=r"(r[3]) : "r"(addr));
}

__device__ __forceinline__ void mma16816(float* c, const uint32_t* a,
                                         uint32_t b0, uint32_t b1) {
    asm volatile(
        "mma.sync.aligned.m16n8k16.row.col.f32.f16.f16.f32 "
        "{%0,%1,%2,%3}, {%4,%5,%6,%7}, {%8,%9}, {%0,%1,%2,%3};"
        : "+f"(c[0]), "+f"(c[1]), "+f"(c[2]), "+f"(c[3])
        : "r"(a[0]), "r"(a[1]), "r"(a[2]), "r"(a[3]), "r"(b0), "r"(b1));
}

// conv geometry: CP=16 channel pairs (32 channels), 16 workers x 8 outputs
#define CLT 128
#define CP  16
#define CHROWS (CLT + 128)

typedef unsigned long long ull;

__device__ __forceinline__ void ffma2(ull& d, ull a, ull b) {
    asm("fma.rn.f32x2 %0, %1, %2, %0;" : "+l"(d) : "l"(a), "l"(b));
}
__device__ __forceinline__ float2 unpack2(ull v) {
    float2 r;
    asm("mov.b64 {%0,%1}, %2;" : "=f"(r.x), "=f"(r.y) : "l"(v));
    return r;
}

__device__ void gemm_part(char* sm, const float* __restrict__ bp, int t)
{
    const uint32_t sbase = smem_u32(sm);
    const uint32_t fmb   = sbase + SM_FMB;
    const uint32_t emb   = sbase + SM_EMB;
    const int tid  = threadIdx.x;
    const int lane = tid & 31;
    const int warp = tid >> 5;
    const int wm = warp >> 1;     // 0..3  M 32-row slab
    const int wn = warp & 1;      // 0..1  N 32-col slab

    const int tile_m = t >> 4;
    const int tile_n = t & 15;
    const int m0 = tile_m * 128;
    const int n0 = tile_n * 64;

    float c[2][4][4];
    #pragma unroll
    for (int i = 0; i < 2; i++)
        #pragma unroll
        for (int j = 0; j < 4; j++)
            #pragma unroll
            for (int r = 0; r < 4; r++) c[i][j][r] = 0.0f;

    // ldmatrix per-lane offsets (swizzled, 64B rows), relative to block bases
    int offA[2][2], offB[2][2];
    {
        const int c0a = (lane >> 4) & 1;
        const int c0b = (lane >> 3) & 1;
        #pragma unroll
        for (int mt = 0; mt < 2; mt++) {
            int rA = wm * 32 + mt * 16 + (lane & 7) + ((lane >> 3) & 1) * 8;
            int sw = (rA >> 1) & 3;
            #pragma unroll
            for (int kk = 0; kk < 2; kk++)
                offA[mt][kk] = rA * 64 + (((c0a | (kk << 1)) ^ sw) << 4);
        }
        #pragma unroll
        for (int bh = 0; bh < 2; bh++) {
            int rB = wn * 32 + bh * 16 + (lane & 7) + ((lane >> 4) & 1) * 8;
            int sw = (rB >> 1) & 3;
            #pragma unroll
            for (int kk = 0; kk < 2; kk++)
                offB[bh][kk] = rB * 64 + (((c0b | (kk << 1)) ^ sw) << 4);
        }
    }

    const char* Abase = (const char*)g_Uh + (size_t)tile_m * 32 * 8192;
    const char* Bbase = (const char*)g_Wh + (size_t)tile_n * 32 * 4096;

    if (tid == 0) {
        #pragma unroll
        for (int i = 0; i < 2; i++) {
            MBAR_INIT(fmb + i * 8, 1);    // tx-based completion
            MBAR_INIT(emb + i * 8, 8);    // one arrival per warp
        }
        asm volatile("fence.proxy.async.shared::cta;" ::: "memory");
        #pragma unroll
        for (int k0 = 0; k0 < 2; k0++) {
            MBAR_EXPECT_TX(fmb + k0 * 8, STAGE_SZ);
            bulk_cp(sbase + k0 * STAGE_SZ,
                    Abase + (size_t)k0 * 16384, 16384, fmb + k0 * 8);
            bulk_cp(sbase + k0 * STAGE_SZ + 16384,
                    Bbase + (size_t)k0 * 8192,  8192,  fmb + k0 * 8);
        }
    }
    __syncthreads();   // one-time: mbar init visible before any waits

    for (int it = 0; it < NITER; it++) {
        const int s = it & 1;
        MBAR_WAIT(fmb + s * 8, (it >> 1) & 1);

        const uint32_t stage = sbase + s * STAGE_SZ;
        #pragma unroll
        for (int kh = 0; kh < 2; kh++) {           // 2 kc per stage
            const uint32_t abase = stage + kh * 8192;
            const uint32_t bbase = stage + 16384 + kh * 4096;
            #pragma unroll
            for (int kk = 0; kk < 2; kk++) {
                uint32_t ar[2][4];
                #pragma unroll
                for (int mt = 0; mt < 2; mt++)
                    ldmatrix4(ar[mt], abase + offA[mt][kk]);
                #pragma unroll
                for (int bh = 0; bh < 2; bh++) {
                    uint32_t br[4];
                    ldmatrix4(br, bbase + offB[bh][kk]);
                    #pragma unroll
                    for (int mt = 0; mt < 2; mt++) {
                        mma16816(c[mt][2 * bh + 0], ar[mt], br[0], br[1]);
                        mma16816(c[mt][2 * bh + 1], ar[mt], br[2], br[3]);
                    }
                }
            }
        }
        // warp done with slot s
        if (lane == 0) MBAR_ARRIVE(emb + s * 8);

        // producer: refill slot s for it+2 after all warps drained it
        if (tid == 0 && it + 2 < NITER) {
            MBAR_WAIT(emb + s * 8, (it >> 1) & 1);   // includes own arrival
            asm volatile("fence.proxy.async.shared::cta;" ::: "memory");
            MBAR_EXPECT_TX(fmb + s * 8, STAGE_SZ);
            bulk_cp(sbase + s * STAGE_SZ,
                    Abase + (size_t)(it + 2) * 16384, 16384, fmb + s * 8);
            bulk_cp(sbase + s * STAGE_SZ + 16384,
                    Bbase + (size_t)(it + 2) * 8192,  8192,  fmb + s * 8);
        }
    }

    const int g  = lane >> 2;
    const int tq = lane & 3;
    #pragma unroll
    for (int mt = 0; mt < 2; mt++) {
        const int row = m0 + wm * 32 + mt * 16 + g;
        #pragma unroll
        for (int nt = 0; nt < 4; nt++) {
            const int col = n0 + wn * 32 + nt * 8 + tq * 2;
            float2 bb = *(const float2*)(bp + col);
            __half2 h0 = __floats2half2_rn(silu_f(c[mt][nt][0] + bb.x),
                                           silu_f(c[mt][nt][1] + bb.y));
            __half2 h1 = __floats2half2_rn(silu_f(c[mt][nt][2] + bb.x),
                                           silu_f(c[mt][nt][3] + bb.y));
            *(uint32_t*)(g_uprojh + (size_t)row * D_DIM + col)       = *(uint32_t*)&h0;
            *(uint32_t*)(g_uprojh + (size_t)(row + 8) * D_DIM + col) = *(uint32_t*)&h1;
        }
    }

    // release: make uproj stores visible, then flag tile done
    __syncthreads();
    if (tid == 0) {
        int* f = &g_flag[t];
        asm volatile("st.release.gpu.global.b32 [%0], %1;"
                     :: "l"(f), "r"(1) : "memory");
    }
}

__device__ void conv_part(char* smc, int idx,
                          const float* __restrict__ u,
                          const float* __restrict__ w1,
                          const float* __restrict__ b1,
                          const float* __restrict__ w2,
                          const float* __restrict__ b2,
                          float* __restrict__ out)
{
    float2* h_s  = (float2*)smc;                              // [256][16]
    float2* w2_s = (float2*)(smc + CHROWS * CP * 8);          // [128][16]

    const int tid = threadIdx.x;
    const int c   = tid & 15;
    const int yy  = tid >> 4;

    const int chunk = idx & 31;
    const int lt    = (idx >> 5) & 31;
    const int bb    = idx >> 10;
    const int tile_start = lt * CLT;
    const int p = chunk * CP + c;

    const float2* uf2  = (const float2*)u + (size_t)bb * L_SEQ * 512;
    const float2* w1f2 = (const float2*)w1;
    const float2* w2f2 = (const float2*)w2;

    #pragma unroll
    for (int i = tid; i < 128 * CP; i += 256) {
        int j = i >> 4, cc = i & 15;
        w2_s[j * CP + cc] = w2f2[(size_t)j * 512 + chunk * CP + cc];
    }

    const float2 w1_0 = w1f2[0 * 512 + p];
    const float2 w1_1 = w1f2[1 * 512 + p];
    const float2 w1_2 = w1f2[2 * 512 + p];
    const float2 b1c  = ((const float2*)b1)[p];

    for (int i = tid; i < CHROWS * CP; i += 256) {
        int hl = i >> 4;
        int l  = tile_start - 127 + hl;
        float2 hv = make_float2(0.0f, 0.0f);
        if (l >= 0 && l < L_SEQ) {
            float2 x2 = uf2[(size_t)l * 512 + p];
            float2 x1 = (l >= 1) ? uf2[(size_t)(l - 1) * 512 + p] : make_float2(0.f, 0.f);
            float2 x0 = (l >= 2) ? uf2[(size_t)(l - 2) * 512 + p] : make_float2(0.f, 0.f);
            float vx = fmaf(x0.x, w1_0.x, fmaf(x1.x, w1_1.x, fmaf(x2.x, w1_2.x, b1c.x)));
            float vy = fmaf(x0.y, w1_0.y, fmaf(x1.y, w1_1.y, fmaf(x2.y, w1_2.y, b1c.y)));
            hv.x = silu_f(vx);
            hv.y = silu_f(vy);
        }
        h_s[hl * CP + c] = hv;
    }
    __syncthreads();

    const int base = yy * 8;
    ull acc[8], win[8];
    #pragma unroll
    for (int r = 0; r < 8; r++) {
        acc[r] = 0ULL;
        win[r] = *(const ull*)&h_s[(base + r) * CP + c];
    }
    #pragma unroll 8
    for (int j = 0; j < 128; j++) {
        ull w = *(const ull*)&w2_s[j * CP + c];
        #pragma unroll
        for (int r = 0; r < 8; r++)
            ffma2(acc[r], win[(j + r) & 7], w);
        win[j & 7] = *(const ull*)&h_s[(base + j + 8) * CP + c];
    }

    // wait for producing GEMM tile (scheduled ~2.6 waves earlier; w.h.p. done)
    const int t_needed = (bb * 32 + lt) * 16 + (chunk >> 1);
    if (tid == 0) {
        const int* f = &g_flag[t_needed];
        int v;
        do {
            asm volatile("ld.acquire.gpu.global.b32 %0, [%1];"
                         : "=r"(v) : "l"(f) : "memory");
            if (!v) __nanosleep(64);
        } while (!v);
    }
    __syncthreads();

    const float2 b2c = ((const float2*)b2)[p];
    const uint32_t* upf = (const uint32_t*)g_uprojh
                          + ((size_t)bb * L_SEQ + tile_start) * 512 + p;
    float2* opf2 = (float2*)out + ((size_t)bb * L_SEQ + tile_start) * 512 + p;

    #pragma unroll
    for (int r = 0; r < 8; r++) {
        float2 a = unpack2(acc[r]);
        int lo   = base + r;
        uint32_t ph = upf[(size_t)lo * 512];
        float2 pr = __half22float2(*(__half2*)&ph);
        float2 y;
        y.x = (a.x + b2c.x) * pr.x;
        y.y = (a.y + b2c.y) * pr.y;
        opf2[(size_t)lo * 512] = y;
    }
}

__global__ void __launch_bounds__(256, 4)
hetero_kernel(const float* __restrict__ u,
              const float* __restrict__ w1,
              const float* __restrict__ b1,
              const float* __restrict__ w2,
              const float* __restrict__ b2,
              const float* __restrict__ bp,
              float* __restrict__ out)
{
    extern __shared__ __align__(128) char sm[];
    const int bid = blockIdx.x;
    if (bid < 512) {
        gemm_part(sm, bp, bid);
    } else if (bid < 5120) {
        const int q = (bid - 512) / 3;
        const int r = (bid - 512) - q * 3;
        if (r == 0)
            gemm_part(sm, bp, 512 + q);
        else
            conv_part(sm, q * 2 + (r - 1), u, w1, b1, w2, b2, out);
    } else {
        conv_part(sm, 3072 + (bid - 5120), u, w1, b1, w2, b2, out);
    }
}

// ---------------------------------------------------------------------------
extern "C" void kernel_launch(void* const* d_in, const int* in_sizes, int n_in,
                              void* d_out, int out_size)
{
    const float* u  = (const float*)d_in[0];
    const float* w1 = (const float*)d_in[1];
    const float* b1 = (const float*)d_in[2];
    const float* w2 = (const float*)d_in[3];
    const float* b2 = (const float*)d_in[4];
    const float* Wp = (const float*)d_in[5];
    const float* bp = (const float*)d_in[6];
    float* out = (float*)d_out;

    cudaFuncSetAttribute(hetero_kernel,
                         cudaFuncAttributeMaxDynamicSharedMemorySize, HET_SMEM);

    convert_kernel<<<2048, 256>>>(u, Wp);
    hetero_kernel<<<TOTAL_CTAS, 256, HET_SMEM>>>(u, w1, b1, w2, b2, bp, out);
}